// round 5
// baseline (speedup 1.0000x reference)
#include <cuda_runtime.h>
#include <cuda_fp16.h>
#include <cstdint>

#define NMAX 50000
#define HD   128
#define BM   128
#define GT   512                   // GEMM threads (16 warps)
#define SLICE 1028                 // words per k-slice: 128*8 + 4 pad
#define WORDS (16 * SLICE)         // 16448 words per A-tile / per W

__device__ float  g_wp [6][WORDS];       // pre-permuted tf32 weights
__device__ __half g_mh [NMAX * HD];      // pool messages (fp16)
__device__ float  g_agg[NMAX * HD];
__device__ float  g_h1 [NMAX * HD];
__device__ int    g_rs [NMAX + 1];

__device__ __forceinline__ uint32_t f2tf32(float x) {
    uint32_t r;
    asm("cvt.rna.tf32.f32 %0, %1;" : "=r"(r) : "f"(x));
    return r;
}

__device__ __forceinline__ void mma_tf32(float c[4], uint32_t a0, uint32_t a1,
                                         uint32_t a2, uint32_t a3,
                                         uint32_t b0, uint32_t b1) {
    asm volatile(
        "mma.sync.aligned.m16n8k8.row.col.f32.tf32.tf32.f32 "
        "{%0,%1,%2,%3}, {%4,%5,%6,%7}, {%8,%9}, {%0,%1,%2,%3};"
        : "+f"(c[0]), "+f"(c[1]), "+f"(c[2]), "+f"(c[3])
        : "r"(a0), "r"(a1), "r"(a2), "r"(a3), "r"(b0), "r"(b1));
}

// ---------------------------------------------------------------------------
// Weight prep: fp32 W[k][col] -> tf32 fragment layout:
// word(k,col) = ks*SLICE + col*8 + tg*2 + h   (k = ks*8 + tg + 4h)
// ---------------------------------------------------------------------------
__global__ void prep_w(const float* w0, const float* w1, const float* w2,
                       const float* w3, const float* w4, const float* w5)
{
    const float* W;
    switch (blockIdx.y) {
        case 0: W = w0; break; case 1: W = w1; break; case 2: W = w2; break;
        case 3: W = w3; break; case 4: W = w4; break; default: W = w5; break;
    }
    int t = blockIdx.x * blockDim.x + threadIdx.x;     // 0..8191
    int ks  = t >> 9;
    int col = (t >> 2) & 127;
    int tg  = t & 3;
    float2 o;
    o.x = __uint_as_float(f2tf32(W[(ks * 8 + tg    ) * HD + col]));
    o.y = __uint_as_float(f2tf32(W[(ks * 8 + tg + 4) * HD + col]));
    *(float2*)&g_wp[blockIdx.y][ks * SLICE + col * 8 + tg * 2] = o;
}

// ---------------------------------------------------------------------------
// Stage A tile (BM x 128) into fragment-layout smem (tf32 bits). 512 threads.
// ---------------------------------------------------------------------------
template<bool GATHER>
__device__ __forceinline__ void stage_A(const float* __restrict__ A,
                                        const int* __restrict__ gidx,
                                        int row0, int nrows, float* As)
{
    const int tid = threadIdx.x;
    #pragma unroll
    for (int i = 0; i < 4; i++) {
        int idx = i * GT + tid;             // 0..2047
        int r   = idx >> 4;                 // 0..127
        int ks  = idx & 15;
        float4 v0 = make_float4(0.f,0.f,0.f,0.f);
        float4 v1 = v0;
        int grow = row0 + r;
        if (grow < nrows) {
            int arow = GATHER ? __ldg(&gidx[grow]) : grow;
            const float4* rp = (const float4*)(A + (size_t)arow * HD);
            v0 = rp[2 * ks];
            v1 = rp[2 * ks + 1];
        }
        float* d = As + ks * SLICE + r * 8;
        float4 s0, s1;
        s0.x = __uint_as_float(f2tf32(v0.x)); s0.y = __uint_as_float(f2tf32(v1.x));
        s0.z = __uint_as_float(f2tf32(v0.y)); s0.w = __uint_as_float(f2tf32(v1.y));
        s1.x = __uint_as_float(f2tf32(v0.z)); s1.y = __uint_as_float(f2tf32(v1.z));
        s1.z = __uint_as_float(f2tf32(v0.w)); s1.w = __uint_as_float(f2tf32(v1.w));
        *(float4*)(d)     = s0;
        *(float4*)(d + 4) = s1;
    }
}

// ---------------------------------------------------------------------------
// Fused dual-W GEMM: m = relu(A@W0 + b0) (fp16), self = A@W1 + b1 (fp32)
// 16 warps, each a 32x32 output tile per weight.
// ---------------------------------------------------------------------------
template<bool GATHER>
__global__ __launch_bounds__(GT, 1)
void gemm_fused(const float* __restrict__ A, const int* __restrict__ gidx,
                int w0i, int w1i,
                const float* __restrict__ b0, const float* __restrict__ b1,
                __half* __restrict__ m_out, float* __restrict__ self_out,
                int nrows)
{
    extern __shared__ float smem[];
    float* As  = smem;
    float* Wp0 = smem + WORDS;
    float* Wp1 = smem + 2 * WORDS;

    const int tid  = threadIdx.x;
    const int row0 = blockIdx.x * BM;

    {   // copy pre-permuted weights (4112 float4 each)
        const float4* s0 = (const float4*)g_wp[w0i];
        const float4* s1 = (const float4*)g_wp[w1i];
        float4* d0 = (float4*)Wp0;
        float4* d1 = (float4*)Wp1;
        #pragma unroll
        for (int i = 0; i < 9; i++) {
            int idx = i * GT + tid;
            if (idx < WORDS / 4) { d0[idx] = s0[idx]; d1[idx] = s1[idx]; }
        }
    }
    stage_A<GATHER>(A, gidx, row0, nrows, As);
    __syncthreads();

    const int lane = tid & 31, wid = tid >> 5;
    const int wn = wid & 3;          // 4 col groups of 32
    const int wm = wid >> 2;         // 4 row groups of 32
    const int g = lane >> 2, tg = lane & 3;
    const int R = wm * 32;

    float acc0[2][4][4], acc1[2][4][4];
    #pragma unroll
    for (int mt = 0; mt < 2; mt++)
        #pragma unroll
        for (int nt = 0; nt < 4; nt++)
            #pragma unroll
            for (int i = 0; i < 4; i++) { acc0[mt][nt][i] = 0.f; acc1[mt][nt][i] = 0.f; }

    #pragma unroll
    for (int ks = 0; ks < 16; ks++) {
        const float* as = As + ks * SLICE;
        float2 afA[2], afB[2];
        #pragma unroll
        for (int mt = 0; mt < 2; mt++) {
            int r = R + mt * 16 + g;
            afA[mt] = *(const float2*)(as + r * 8 + tg * 2);
            afB[mt] = *(const float2*)(as + (r + 8) * 8 + tg * 2);
        }
        const float* ws0 = Wp0 + ks * SLICE;
        const float* ws1 = Wp1 + ks * SLICE;
        #pragma unroll
        for (int nt = 0; nt < 4; nt++) {
            int cw = (wn * 32 + nt * 8 + g) * 8 + tg * 2;
            float2 bf0 = *(const float2*)(ws0 + cw);
            float2 bf1 = *(const float2*)(ws1 + cw);
            #pragma unroll
            for (int mt = 0; mt < 2; mt++) {
                mma_tf32(acc0[mt][nt],
                         __float_as_uint(afA[mt].x), __float_as_uint(afB[mt].x),
                         __float_as_uint(afA[mt].y), __float_as_uint(afB[mt].y),
                         __float_as_uint(bf0.x), __float_as_uint(bf0.y));
                mma_tf32(acc1[mt][nt],
                         __float_as_uint(afA[mt].x), __float_as_uint(afB[mt].x),
                         __float_as_uint(afA[mt].y), __float_as_uint(afB[mt].y),
                         __float_as_uint(bf1.x), __float_as_uint(bf1.y));
            }
        }
    }

    float2 bv0[4], bv1[4];
    #pragma unroll
    for (int nt = 0; nt < 4; nt++) {
        int col = wn * 32 + nt * 8 + 2 * tg;
        bv0[nt] = *(const float2*)(b0 + col);
        bv1[nt] = *(const float2*)(b1 + col);
    }

    #pragma unroll
    for (int mt = 0; mt < 2; mt++) {
        #pragma unroll
        for (int hh = 0; hh < 2; hh++) {
            int grow = row0 + R + mt * 16 + g + hh * 8;
            if (grow >= nrows) continue;
            #pragma unroll
            for (int nt = 0; nt < 4; nt++) {
                int col = wn * 32 + nt * 8 + 2 * tg;
                float mx = fmaxf(acc0[mt][nt][hh*2+0] + bv0[nt].x, 0.f);
                float my = fmaxf(acc0[mt][nt][hh*2+1] + bv0[nt].y, 0.f);
                *(__half2*)(m_out + (size_t)grow * HD + col) =
                    __floats2half2_rn(mx, my);
                float2 s;
                s.x = acc1[mt][nt][hh*2+0] + bv1[nt].x;
                s.y = acc1[mt][nt][hh*2+1] + bv1[nt].y;
                *(float2*)(self_out + (size_t)grow * HD + col) = s;
            }
        }
    }
}

// ---------------------------------------------------------------------------
// Accumulate GEMM: out += A @ W   (16 warps, 32x32 per warp)
// ---------------------------------------------------------------------------
__global__ __launch_bounds__(GT, 1)
void gemm_acc(const float* __restrict__ A, int wi, float* __restrict__ out,
              int nrows)
{
    extern __shared__ float smem[];
    float* As = smem;
    float* Wp = smem + WORDS;

    const int tid  = threadIdx.x;
    const int row0 = blockIdx.x * BM;

    {
        const float4* s = (const float4*)g_wp[wi];
        float4* d = (float4*)Wp;
        #pragma unroll
        for (int i = 0; i < 9; i++) {
            int idx = i * GT + tid;
            if (idx < WORDS / 4) d[idx] = s[idx];
        }
    }
    stage_A<false>(A, nullptr, row0, nrows, As);
    __syncthreads();

    const int lane = tid & 31, wid = tid >> 5;
    const int wn = wid & 3;
    const int wm = wid >> 2;
    const int g = lane >> 2, tg = lane & 3;
    const int R = wm * 32;

    float acc[2][4][4];
    #pragma unroll
    for (int mt = 0; mt < 2; mt++)
        #pragma unroll
        for (int nt = 0; nt < 4; nt++)
            #pragma unroll
            for (int i = 0; i < 4; i++) acc[mt][nt][i] = 0.f;

    #pragma unroll
    for (int ks = 0; ks < 16; ks++) {
        const float* as = As + ks * SLICE;
        float2 afA[2], afB[2];
        #pragma unroll
        for (int mt = 0; mt < 2; mt++) {
            int r = R + mt * 16 + g;
            afA[mt] = *(const float2*)(as + r * 8 + tg * 2);
            afB[mt] = *(const float2*)(as + (r + 8) * 8 + tg * 2);
        }
        const float* ws = Wp + ks * SLICE;
        #pragma unroll
        for (int nt = 0; nt < 4; nt++) {
            int cw = (wn * 32 + nt * 8 + g) * 8 + tg * 2;
            float2 bf = *(const float2*)(ws + cw);
            #pragma unroll
            for (int mt = 0; mt < 2; mt++)
                mma_tf32(acc[mt][nt],
                         __float_as_uint(afA[mt].x), __float_as_uint(afB[mt].x),
                         __float_as_uint(afA[mt].y), __float_as_uint(afB[mt].y),
                         __float_as_uint(bf.x), __float_as_uint(bf.y));
        }
    }

    #pragma unroll
    for (int mt = 0; mt < 2; mt++) {
        #pragma unroll
        for (int hh = 0; hh < 2; hh++) {
            int grow = row0 + R + mt * 16 + g + hh * 8;
            if (grow >= nrows) continue;
            #pragma unroll
            for (int nt = 0; nt < 4; nt++) {
                int col = wn * 32 + nt * 8 + 2 * tg;
                float2 p = *(const float2*)(out + (size_t)grow * HD + col);
                p.x += acc[mt][nt][hh*2+0];
                p.y += acc[mt][nt][hh*2+1];
                *(float2*)(out + (size_t)grow * HD + col) = p;
            }
        }
    }
}

// ---------------------------------------------------------------------------
__global__ void csr_offsets(const int* __restrict__ dst, int* __restrict__ rs,
                            int nE, int nN)
{
    int n = blockIdx.x * blockDim.x + threadIdx.x;
    if (n > nN) return;
    if (n == nN) { rs[n] = nE; return; }
    int lo = 0, hi = nE;
    while (lo < hi) {
        int mid = (lo + hi) >> 1;
        if (__ldg(&dst[mid]) < n) lo = mid + 1; else hi = mid;
    }
    rs[n] = lo;
}

// ---------------------------------------------------------------------------
// Segmented max over fp16 messages; software-pipelined x4 (MLP=4).
// ---------------------------------------------------------------------------
__global__ __launch_bounds__(256)
void seg_max_h(const __half* __restrict__ m, const int* __restrict__ src,
               const int* __restrict__ rs, float* __restrict__ agg, int nN)
{
    int warp = (blockIdx.x * blockDim.x + threadIdx.x) >> 5;
    int lane = threadIdx.x & 31;
    if (warp >= nN) return;

    int e0 = __ldg(&rs[warp]);
    int e1 = __ldg(&rs[warp + 1]);

    const __half2 z = __float2half2_rn(0.f);
    __half2 a0 = z, a1 = z;
    const uint2* m2 = (const uint2*)m;

    for (int eb = e0; eb < e1; eb += 32) {
        int cnt = min(32, e1 - eb);
        int s_l = (lane < cnt) ? __ldg(&src[eb + lane]) : 0;
        int i = 0;
        #pragma unroll 1
        for (; i + 4 <= cnt; i += 4) {
            int s0 = __shfl_sync(0xffffffffu, s_l, i);
            int s1 = __shfl_sync(0xffffffffu, s_l, i + 1);
            int s2 = __shfl_sync(0xffffffffu, s_l, i + 2);
            int s3 = __shfl_sync(0xffffffffu, s_l, i + 3);
            uint2 v0 = __ldg(&m2[(size_t)s0 * 32 + lane]);
            uint2 v1 = __ldg(&m2[(size_t)s1 * 32 + lane]);
            uint2 v2 = __ldg(&m2[(size_t)s2 * 32 + lane]);
            uint2 v3 = __ldg(&m2[(size_t)s3 * 32 + lane]);
            __half2 t0 = __hmax2(*(__half2*)&v0.x, *(__half2*)&v1.x);
            __half2 t1 = __hmax2(*(__half2*)&v2.x, *(__half2*)&v3.x);
            a0 = __hmax2(a0, __hmax2(t0, t1));
            __half2 u0 = __hmax2(*(__half2*)&v0.y, *(__half2*)&v1.y);
            __half2 u1 = __hmax2(*(__half2*)&v2.y, *(__half2*)&v3.y);
            a1 = __hmax2(a1, __hmax2(u0, u1));
        }
        #pragma unroll 1
        for (; i < cnt; i++) {
            int s = __shfl_sync(0xffffffffu, s_l, i);
            uint2 v = __ldg(&m2[(size_t)s * 32 + lane]);
            a0 = __hmax2(a0, *(__half2*)&v.x);
            a1 = __hmax2(a1, *(__half2*)&v.y);
        }
    }
    float2 f0 = __half22float2(a0);
    float2 f1 = __half22float2(a1);
    float4 o = make_float4(f0.x, f0.y, f1.x, f1.y);
    ((float4*)agg)[(size_t)warp * 32 + lane] = o;
}

// ---------------------------------------------------------------------------
extern "C" void kernel_launch(void* const* d_in, const int* in_sizes, int n_in,
                              void* d_out, int out_size)
{
    const int*   node_ids = (const int*)  d_in[0];
    const int*   src      = (const int*)  d_in[1];
    const int*   dst      = (const int*)  d_in[2];
    const float* emb      = (const float*)d_in[3];
    const float* W_pool1  = (const float*)d_in[4];
    const float* b_pool1  = (const float*)d_in[5];
    const float* W_self1  = (const float*)d_in[6];
    const float* W_neigh1 = (const float*)d_in[7];
    const float* b1       = (const float*)d_in[8];
    const float* W_pool2  = (const float*)d_in[9];
    const float* b_pool2  = (const float*)d_in[10];
    const float* W_self2  = (const float*)d_in[11];
    const float* W_neigh2 = (const float*)d_in[12];
    const float* b2       = (const float*)d_in[13];
    float*       out      = (float*)d_out;

    const int nN = in_sizes[0];
    const int nE = in_sizes[1];

    __half* mh;  float *agg, *h1;  int *rs;
    cudaGetSymbolAddress((void**)&mh,  g_mh);
    cudaGetSymbolAddress((void**)&agg, g_agg);
    cudaGetSymbolAddress((void**)&h1,  g_h1);
    cudaGetSymbolAddress((void**)&rs,  g_rs);

    const int SMEM3 = 3 * WORDS * (int)sizeof(float);   // 197376
    const int SMEM2 = 2 * WORDS * (int)sizeof(float);   // 131584

    cudaFuncSetAttribute(gemm_fused<true >, cudaFuncAttributeMaxDynamicSharedMemorySize, SMEM3);
    cudaFuncSetAttribute(gemm_fused<false>, cudaFuncAttributeMaxDynamicSharedMemorySize, SMEM3);
    cudaFuncSetAttribute(gemm_acc,          cudaFuncAttributeMaxDynamicSharedMemorySize, SMEM2);

    const int gemm_blocks = (nN + BM - 1) / BM;
    const int csr_blocks  = (nN + 1 + 255) / 256;
    const int seg_blocks  = (nN + 7) / 8;

    prep_w<<<dim3(32, 6), 256>>>(W_pool1, W_self1, W_neigh1, W_pool2, W_self2, W_neigh2);
    csr_offsets<<<csr_blocks, 256>>>(dst, rs, nE, nN);

    // ---- Layer 1 ----
    gemm_fused<true><<<gemm_blocks, GT, SMEM3>>>(
        emb, node_ids, 0, 1, b_pool1, b1, mh, h1, nN);
    seg_max_h<<<seg_blocks, 256>>>(mh, src, rs, agg, nN);
    gemm_acc<<<gemm_blocks, GT, SMEM2>>>(agg, 2, h1, nN);

    // ---- Layer 2 ----
    gemm_fused<false><<<gemm_blocks, GT, SMEM3>>>(
        h1, nullptr, 3, 4, b_pool2, b2, mh, out, nN);
    seg_max_h<<<seg_blocks, 256>>>(mh, src, rs, agg, nN);
    gemm_acc<<<gemm_blocks, GT, SMEM2>>>(agg, 5, out, nN);
}

// round 6
// speedup vs baseline: 1.2386x; 1.2386x over previous
#include <cuda_runtime.h>
#include <cuda_fp16.h>
#include <cstdint>

#define NMAX 50000
#define HD   128
#define BM   128
#define GT   512                   // GEMM threads (16 warps)
#define ASLICE 2056                // halfs per k16-slice: 128*16 + 8 pad
#define WSLICE 2056
#define NKS    8                   // 128 / 16
#define WHALF  (NKS * WSLICE)      // 16448 halfs per weight / A tile

__device__ __half g_wph[6][WHALF];       // pre-permuted fp16 weights (fragment order)
__device__ __half g_mh [NMAX * HD];      // pool messages (fp16)
__device__ float  g_agg[NMAX * HD];
__device__ float  g_h1 [NMAX * HD];
__device__ int    g_rs [NMAX + 1];

__device__ __forceinline__ void mma_f16(float c[4], uint32_t a0, uint32_t a1,
                                        uint32_t a2, uint32_t a3,
                                        uint32_t b0, uint32_t b1) {
    asm volatile(
        "mma.sync.aligned.m16n8k16.row.col.f32.f16.f16.f32 "
        "{%0,%1,%2,%3}, {%4,%5,%6,%7}, {%8,%9}, {%0,%1,%2,%3};"
        : "+f"(c[0]), "+f"(c[1]), "+f"(c[2]), "+f"(c[3])
        : "r"(a0), "r"(a1), "r"(a2), "r"(a3), "r"(b0), "r"(b1));
}

__device__ __forceinline__ uint32_t pack_h2(float lo, float hi) {
    __half2 h = __floats2half2_rn(lo, hi);
    return *(uint32_t*)&h;
}

// ---------------------------------------------------------------------------
// Weight prep: W[k][col] fp32 -> fp16 fragment layout.
// halfs at ks*WSLICE + col*16 + tg*4 = {k=2tg, 2tg+1, 2tg+8, 2tg+9} (k local to ks*16)
// ---------------------------------------------------------------------------
__global__ void prep_w(const float* w0, const float* w1, const float* w2,
                       const float* w3, const float* w4, const float* w5)
{
    const float* W;
    switch (blockIdx.y) {
        case 0: W = w0; break; case 1: W = w1; break; case 2: W = w2; break;
        case 3: W = w3; break; case 4: W = w4; break; default: W = w5; break;
    }
    int t = blockIdx.x * blockDim.x + threadIdx.x;   // 0..4095
    int ks  = t >> 9;
    int rem = t & 511;
    int col = rem >> 2;
    int tg  = rem & 3;
    int k0  = ks * 16 + 2 * tg;
    uint2 o;
    o.x = pack_h2(W[(k0    ) * HD + col], W[(k0 + 1) * HD + col]);
    o.y = pack_h2(W[(k0 + 8) * HD + col], W[(k0 + 9) * HD + col]);
    *(uint2*)(&g_wph[blockIdx.y][ks * WSLICE + col * 16 + tg * 4]) = o;
}

// ---------------------------------------------------------------------------
// Stage A tile (BM x 128 fp32) into fp16 fragment-layout smem. 512 threads.
// ---------------------------------------------------------------------------
template<bool GATHER>
__device__ __forceinline__ void stage_A_h(const float* __restrict__ A,
                                          const int* __restrict__ gidx,
                                          int row0, int nrows, __half* As)
{
    const int tid = threadIdx.x;
    #pragma unroll
    for (int i = 0; i < 2; i++) {
        int idx = i * GT + tid;             // 0..1023 cells (row, ks)
        int r   = idx >> 3;
        int ks  = idx & 7;
        float4 f0 = make_float4(0.f,0.f,0.f,0.f), f1 = f0, f2 = f0, f3 = f0;
        int grow = row0 + r;
        if (grow < nrows) {
            int arow = GATHER ? __ldg(&gidx[grow]) : grow;
            const float4* rp = (const float4*)(A + (size_t)arow * HD) + ks * 4;
            f0 = rp[0]; f1 = rp[1]; f2 = rp[2]; f3 = rp[3];
        }
        uint4 q0, q1;
        q0.x = pack_h2(f0.x, f0.y);  q0.y = pack_h2(f2.x, f2.y);
        q0.z = pack_h2(f0.z, f0.w);  q0.w = pack_h2(f2.z, f2.w);
        q1.x = pack_h2(f1.x, f1.y);  q1.y = pack_h2(f3.x, f3.y);
        q1.z = pack_h2(f1.z, f1.w);  q1.w = pack_h2(f3.z, f3.w);
        __half* d = As + ks * ASLICE + r * 16;
        *(uint4*)(d)     = q0;
        *(uint4*)(d + 8) = q1;
    }
}

// ---------------------------------------------------------------------------
// Fused dual-W GEMM: m = relu(A@W0 + b0) (fp16), self = A@W1 + b1 (fp32)
// ---------------------------------------------------------------------------
template<bool GATHER>
__global__ __launch_bounds__(GT, 1)
void gemm_fused(const float* __restrict__ A, const int* __restrict__ gidx,
                int w0i, int w1i,
                const float* __restrict__ b0, const float* __restrict__ b1,
                __half* __restrict__ m_out, float* __restrict__ self_out,
                int nrows)
{
    extern __shared__ __half smh[];
    __half* As  = smh;
    __half* Wp0 = smh + WHALF;
    __half* Wp1 = smh + 2 * WHALF;

    const int tid  = threadIdx.x;
    const int row0 = blockIdx.x * BM;

    {   // copy both pre-permuted weights (2056 uint4 each)
        const uint4* s0 = (const uint4*)g_wph[w0i];
        const uint4* s1 = (const uint4*)g_wph[w1i];
        uint4* d0 = (uint4*)Wp0;
        uint4* d1 = (uint4*)Wp1;
        #pragma unroll
        for (int i = 0; i < 5; i++) {
            int idx = i * GT + tid;
            if (idx < WHALF / 8) { d0[idx] = s0[idx]; d1[idx] = s1[idx]; }
        }
    }
    stage_A_h<GATHER>(A, gidx, row0, nrows, As);
    __syncthreads();

    const int lane = tid & 31, wid = tid >> 5;
    const int wn = wid & 3;          // 4 col groups of 32
    const int wm = wid >> 2;         // 4 row groups of 32
    const int g = lane >> 2, tg = lane & 3;
    const int R = wm * 32;

    float acc0[2][4][4], acc1[2][4][4];
    #pragma unroll
    for (int mt = 0; mt < 2; mt++)
        #pragma unroll
        for (int nt = 0; nt < 4; nt++)
            #pragma unroll
            for (int i = 0; i < 4; i++) { acc0[mt][nt][i] = 0.f; acc1[mt][nt][i] = 0.f; }

    #pragma unroll
    for (int ks = 0; ks < NKS; ks++) {
        const __half* ap = As + ks * ASLICE;
        uint2 va[2], vb[2];
        #pragma unroll
        for (int mt = 0; mt < 2; mt++) {
            int row = R + mt * 16 + g;
            va[mt] = *(const uint2*)(ap + row * 16 + tg * 4);
            vb[mt] = *(const uint2*)(ap + (row + 8) * 16 + tg * 4);
        }
        const __half* w0p = Wp0 + ks * WSLICE;
        const __half* w1p = Wp1 + ks * WSLICE;
        #pragma unroll
        for (int nt = 0; nt < 4; nt++) {
            int col = wn * 32 + nt * 8 + g;
            uint2 u0 = *(const uint2*)(w0p + col * 16 + tg * 4);
            uint2 u1 = *(const uint2*)(w1p + col * 16 + tg * 4);
            #pragma unroll
            for (int mt = 0; mt < 2; mt++) {
                mma_f16(acc0[mt][nt], va[mt].x, vb[mt].x, va[mt].y, vb[mt].y, u0.x, u0.y);
                mma_f16(acc1[mt][nt], va[mt].x, vb[mt].x, va[mt].y, vb[mt].y, u1.x, u1.y);
            }
        }
    }

    float2 bv0[4], bv1[4];
    #pragma unroll
    for (int nt = 0; nt < 4; nt++) {
        int col = wn * 32 + nt * 8 + 2 * tg;
        bv0[nt] = *(const float2*)(b0 + col);
        bv1[nt] = *(const float2*)(b1 + col);
    }

    #pragma unroll
    for (int mt = 0; mt < 2; mt++) {
        #pragma unroll
        for (int hh = 0; hh < 2; hh++) {
            int grow = row0 + R + mt * 16 + g + hh * 8;
            if (grow >= nrows) continue;
            #pragma unroll
            for (int nt = 0; nt < 4; nt++) {
                int col = wn * 32 + nt * 8 + 2 * tg;
                float mx = fmaxf(acc0[mt][nt][hh*2+0] + bv0[nt].x, 0.f);
                float my = fmaxf(acc0[mt][nt][hh*2+1] + bv0[nt].y, 0.f);
                *(__half2*)(m_out + (size_t)grow * HD + col) =
                    __floats2half2_rn(mx, my);
                float2 s;
                s.x = acc1[mt][nt][hh*2+0] + bv1[nt].x;
                s.y = acc1[mt][nt][hh*2+1] + bv1[nt].y;
                *(float2*)(self_out + (size_t)grow * HD + col) = s;
            }
        }
    }
}

// ---------------------------------------------------------------------------
// Accumulate GEMM: out += A @ W
// ---------------------------------------------------------------------------
__global__ __launch_bounds__(GT, 1)
void gemm_acc(const float* __restrict__ A, int wi, float* __restrict__ out,
              int nrows)
{
    extern __shared__ __half smh[];
    __half* As = smh;
    __half* Wp = smh + WHALF;

    const int tid  = threadIdx.x;
    const int row0 = blockIdx.x * BM;

    {
        const uint4* s = (const uint4*)g_wph[wi];
        uint4* d = (uint4*)Wp;
        #pragma unroll
        for (int i = 0; i < 5; i++) {
            int idx = i * GT + tid;
            if (idx < WHALF / 8) d[idx] = s[idx];
        }
    }
    stage_A_h<false>(A, nullptr, row0, nrows, As);
    __syncthreads();

    const int lane = tid & 31, wid = tid >> 5;
    const int wn = wid & 3;
    const int wm = wid >> 2;
    const int g = lane >> 2, tg = lane & 3;
    const int R = wm * 32;

    float acc[2][4][4];
    #pragma unroll
    for (int mt = 0; mt < 2; mt++)
        #pragma unroll
        for (int nt = 0; nt < 4; nt++)
            #pragma unroll
            for (int i = 0; i < 4; i++) acc[mt][nt][i] = 0.f;

    #pragma unroll
    for (int ks = 0; ks < NKS; ks++) {
        const __half* ap = As + ks * ASLICE;
        uint2 va[2], vb[2];
        #pragma unroll
        for (int mt = 0; mt < 2; mt++) {
            int row = R + mt * 16 + g;
            va[mt] = *(const uint2*)(ap + row * 16 + tg * 4);
            vb[mt] = *(const uint2*)(ap + (row + 8) * 16 + tg * 4);
        }
        const __half* wp = Wp + ks * WSLICE;
        #pragma unroll
        for (int nt = 0; nt < 4; nt++) {
            int col = wn * 32 + nt * 8 + g;
            uint2 u = *(const uint2*)(wp + col * 16 + tg * 4);
            #pragma unroll
            for (int mt = 0; mt < 2; mt++)
                mma_f16(acc[mt][nt], va[mt].x, vb[mt].x, va[mt].y, vb[mt].y, u.x, u.y);
        }
    }

    #pragma unroll
    for (int mt = 0; mt < 2; mt++) {
        #pragma unroll
        for (int hh = 0; hh < 2; hh++) {
            int grow = row0 + R + mt * 16 + g + hh * 8;
            if (grow >= nrows) continue;
            #pragma unroll
            for (int nt = 0; nt < 4; nt++) {
                int col = wn * 32 + nt * 8 + 2 * tg;
                float2 p = *(const float2*)(out + (size_t)grow * HD + col);
                p.x += acc[mt][nt][hh*2+0];
                p.y += acc[mt][nt][hh*2+1];
                *(float2*)(out + (size_t)grow * HD + col) = p;
            }
        }
    }
}

// ---------------------------------------------------------------------------
__global__ void csr_offsets(const int* __restrict__ dst, int* __restrict__ rs,
                            int nE, int nN)
{
    int n = blockIdx.x * blockDim.x + threadIdx.x;
    if (n > nN) return;
    if (n == nN) { rs[n] = nE; return; }
    int lo = 0, hi = nE;
    while (lo < hi) {
        int mid = (lo + hi) >> 1;
        if (__ldg(&dst[mid]) < n) lo = mid + 1; else hi = mid;
    }
    rs[n] = lo;
}

// ---------------------------------------------------------------------------
// Segmented max over fp16 messages. Unroll-8 with idempotent index clamping:
// duplicated edges are harmless under max, so there is NO serial remainder.
// ---------------------------------------------------------------------------
__global__ __launch_bounds__(256)
void seg_max_h(const __half* __restrict__ m, const int* __restrict__ src,
               const int* __restrict__ rs, float* __restrict__ agg, int nN)
{
    int warp = (blockIdx.x * blockDim.x + threadIdx.x) >> 5;
    int lane = threadIdx.x & 31;
    if (warp >= nN) return;

    int e0 = __ldg(&rs[warp]);
    int e1 = __ldg(&rs[warp + 1]);

    const __half2 z = __float2half2_rn(0.f);
    __half2 a0 = z, a1 = z;
    const uint2* m2 = (const uint2*)m;

    for (int eb = e0; eb < e1; eb += 32) {
        int cnt = min(32, e1 - eb);
        int s_l = __ldg(&src[eb + min(lane, cnt - 1)]);
        #pragma unroll 1
        for (int j = 0; j < cnt; j += 8) {
            int i0 = j,                 i1 = min(j + 1, cnt - 1);
            int i2 = min(j + 2, cnt-1), i3 = min(j + 3, cnt - 1);
            int i4 = min(j + 4, cnt-1), i5 = min(j + 5, cnt - 1);
            int i6 = min(j + 6, cnt-1), i7 = min(j + 7, cnt - 1);
            int s0 = __shfl_sync(0xffffffffu, s_l, i0);
            int s1 = __shfl_sync(0xffffffffu, s_l, i1);
            int s2 = __shfl_sync(0xffffffffu, s_l, i2);
            int s3 = __shfl_sync(0xffffffffu, s_l, i3);
            int s4 = __shfl_sync(0xffffffffu, s_l, i4);
            int s5 = __shfl_sync(0xffffffffu, s_l, i5);
            int s6 = __shfl_sync(0xffffffffu, s_l, i6);
            int s7 = __shfl_sync(0xffffffffu, s_l, i7);
            uint2 v0 = __ldg(&m2[(size_t)s0 * 32 + lane]);
            uint2 v1 = __ldg(&m2[(size_t)s1 * 32 + lane]);
            uint2 v2 = __ldg(&m2[(size_t)s2 * 32 + lane]);
            uint2 v3 = __ldg(&m2[(size_t)s3 * 32 + lane]);
            uint2 v4 = __ldg(&m2[(size_t)s4 * 32 + lane]);
            uint2 v5 = __ldg(&m2[(size_t)s5 * 32 + lane]);
            uint2 v6 = __ldg(&m2[(size_t)s6 * 32 + lane]);
            uint2 v7 = __ldg(&m2[(size_t)s7 * 32 + lane]);
            __half2 x01 = __hmax2(*(__half2*)&v0.x, *(__half2*)&v1.x);
            __half2 x23 = __hmax2(*(__half2*)&v2.x, *(__half2*)&v3.x);
            __half2 x45 = __hmax2(*(__half2*)&v4.x, *(__half2*)&v5.x);
            __half2 x67 = __hmax2(*(__half2*)&v6.x, *(__half2*)&v7.x);
            a0 = __hmax2(a0, __hmax2(__hmax2(x01, x23), __hmax2(x45, x67)));
            __half2 y01 = __hmax2(*(__half2*)&v0.y, *(__half2*)&v1.y);
            __half2 y23 = __hmax2(*(__half2*)&v2.y, *(__half2*)&v3.y);
            __half2 y45 = __hmax2(*(__half2*)&v4.y, *(__half2*)&v5.y);
            __half2 y67 = __hmax2(*(__half2*)&v6.y, *(__half2*)&v7.y);
            a1 = __hmax2(a1, __hmax2(__hmax2(y01, y23), __hmax2(y45, y67)));
        }
    }
    float2 f0 = __half22float2(a0);
    float2 f1 = __half22float2(a1);
    float4 o = make_float4(f0.x, f0.y, f1.x, f1.y);
    ((float4*)agg)[(size_t)warp * 32 + lane] = o;
}

// ---------------------------------------------------------------------------
extern "C" void kernel_launch(void* const* d_in, const int* in_sizes, int n_in,
                              void* d_out, int out_size)
{
    const int*   node_ids = (const int*)  d_in[0];
    const int*   src      = (const int*)  d_in[1];
    const int*   dst      = (const int*)  d_in[2];
    const float* emb      = (const float*)d_in[3];
    const float* W_pool1  = (const float*)d_in[4];
    const float* b_pool1  = (const float*)d_in[5];
    const float* W_self1  = (const float*)d_in[6];
    const float* W_neigh1 = (const float*)d_in[7];
    const float* b1       = (const float*)d_in[8];
    const float* W_pool2  = (const float*)d_in[9];
    const float* b_pool2  = (const float*)d_in[10];
    const float* W_self2  = (const float*)d_in[11];
    const float* W_neigh2 = (const float*)d_in[12];
    const float* b2       = (const float*)d_in[13];
    float*       out      = (float*)d_out;

    const int nN = in_sizes[0];
    const int nE = in_sizes[1];

    __half* mh;  float *agg, *h1;  int *rs;
    cudaGetSymbolAddress((void**)&mh,  g_mh);
    cudaGetSymbolAddress((void**)&agg, g_agg);
    cudaGetSymbolAddress((void**)&h1,  g_h1);
    cudaGetSymbolAddress((void**)&rs,  g_rs);

    const int SMEM3 = 3 * WHALF * (int)sizeof(__half);   // 98688
    const int SMEM2 = 2 * WHALF * (int)sizeof(__half);   // 65792

    cudaFuncSetAttribute(gemm_fused<true >, cudaFuncAttributeMaxDynamicSharedMemorySize, SMEM3);
    cudaFuncSetAttribute(gemm_fused<false>, cudaFuncAttributeMaxDynamicSharedMemorySize, SMEM3);
    cudaFuncSetAttribute(gemm_acc,          cudaFuncAttributeMaxDynamicSharedMemorySize, SMEM2);

    const int gemm_blocks = (nN + BM - 1) / BM;
    const int csr_blocks  = (nN + 1 + 255) / 256;
    const int seg_blocks  = (nN + 7) / 8;

    prep_w<<<dim3(16, 6), 256>>>(W_pool1, W_self1, W_neigh1, W_pool2, W_self2, W_neigh2);
    csr_offsets<<<csr_blocks, 256>>>(dst, rs, nE, nN);

    // ---- Layer 1 ----
    gemm_fused<true><<<gemm_blocks, GT, SMEM3>>>(
        emb, node_ids, 0, 1, b_pool1, b1, mh, h1, nN);
    seg_max_h<<<seg_blocks, 256>>>(mh, src, rs, agg, nN);
    gemm_acc<<<gemm_blocks, GT, SMEM2>>>(agg, 2, h1, nN);

    // ---- Layer 2 ----
    gemm_fused<false><<<gemm_blocks, GT, SMEM3>>>(
        h1, nullptr, 3, 4, b_pool2, b2, mh, out, nN);
    seg_max_h<<<seg_blocks, 256>>>(mh, src, rs, agg, nN);
    gemm_acc<<<gemm_blocks, GT, SMEM2>>>(agg, 5, out, nN);
}